// round 5
// baseline (speedup 1.0000x reference)
#include <cuda_runtime.h>
#include <math.h>

// Problem constants
#define Bsz   128
#define Nn    512
#define GJ    1536          // 3*512 gate columns
#define MROWS (Bsz*Nn)      // 65536
#define NCTA  148           // persistent grid (1 CTA/SM, all resident)

// ---------------- device scratch (allocation-free) ---------------------------
__device__ float g_Ubuf[(size_t)MROWS * GJ];   // emb@ul^T + bias
__device__ float g_LW  [(size_t)MROWS * GJ];   // emb@wl^T
__device__ float g_rlin[(size_t)MROWS * GJ];   // ph@ur^T
__device__ float g_cbuf[(size_t)MROWS * 512];  // cell state
__device__ float g_pooled[(size_t)MROWS * 24]; // pooled bilinear

__device__ int g_level[MROWS];
__device__ int g_lcount[512];
__device__ int g_lstart[513];
__device__ int g_lcur[512];
__device__ int g_nodelist[MROWS];
__device__ int g_maxlev;

__device__ unsigned g_gcnt = 0;
__device__ unsigned g_ggen = 0;

// ---------------- tf32 helpers ----------------------------------------------
__device__ __forceinline__ unsigned f2t(float x) {
    unsigned u; asm("cvt.rna.tf32.f32 %0, %1;" : "=r"(u) : "f"(x)); return u;
}
__device__ __forceinline__ void st_tf32_4(float* dst, float4 v) {
    uint4 u; u.x = f2t(v.x); u.y = f2t(v.y); u.z = f2t(v.z); u.w = f2t(v.w);
    *(uint4*)dst = u;
}
__device__ __forceinline__ void mma8(float* c, const unsigned* a, const unsigned* b) {
    asm volatile(
        "mma.sync.aligned.m16n8k8.row.col.f32.tf32.tf32.f32 "
        "{%0,%1,%2,%3},{%4,%5,%6,%7},{%8,%9},{%0,%1,%2,%3};"
        : "+f"(c[0]), "+f"(c[1]), "+f"(c[2]), "+f"(c[3])
        : "r"(a[0]), "r"(a[1]), "r"(a[2]), "r"(a[3]), "r"(b[0]), "r"(b[1]));
}

// ---------------- level metadata kernels ------------------------------------
__global__ void build_depth(const int* __restrict__ nc) {
    __shared__ int spar[512];
    __shared__ unsigned short dep[512];
    const int b = blockIdx.x;
    for (int t = threadIdx.x; t < 512; t += 32) spar[t] = nc[b * 512 + t];
    __syncthreads();
    if (threadIdx.x == 0) {
        for (int t = 0; t < 512; t++) {
            int par = spar[t];
            dep[t] = (t > 0 && par < t) ? (unsigned short)(dep[par] + 1) : 0;
        }
    }
    __syncthreads();
    for (int t = threadIdx.x; t < 512; t += 32) {
        int lv = dep[t];
        g_level[b * 512 + t] = lv;
        atomicAdd(&g_lcount[lv], 1);
    }
}

__global__ void prefix_levels() {
    int sum = 0, mx = 0;
    for (int l = 0; l < 512; l++) {
        g_lstart[l] = sum;
        g_lcur[l]   = sum;
        if (g_lcount[l] > 0) mx = l;
        sum += g_lcount[l];
        g_lcount[l] = 0;   // re-zero for next replay (statically zero on 1st run)
    }
    g_lstart[512] = sum;
    g_maxlev = mx;
}

__global__ void scatter_levels() {
    int i = blockIdx.x * 512 + threadIdx.x;
    if (i < MROWS) {
        int pos = atomicAdd(&g_lcur[g_level[i]], 1);
        g_nodelist[pos] = i;
    }
}

// ---------------- precompute GEMM (tf32 mma): C[Mx1536] = A[Mx512]@W^T (+bias)
// BM=128, BN=256, BK=16, 256 threads (8 warps: 2m x 4n), warp tile 64x64.
__global__ __launch_bounds__(256) void gemm_pre(
    const float* __restrict__ A, const float* __restrict__ W,
    const float* __restrict__ bias, int sel)
{
    __shared__ float SM[15360];   // As 2x128x20 | Bs 2x256x20 ; epilogue stage 128x68
#define ASP(b,r,k) SM[(b)*2560 + (r)*20 + (k)]
#define BSP(b,r,k) SM[5120 + (b)*5120 + (r)*20 + (k)]

    float* C = sel ? g_LW : g_Ubuf;

    const int tid = threadIdx.x, lane = tid & 31, warp = tid >> 5;
    const int wm = (warp & 1) * 64, wn = (warp >> 1) * 64;
    const int g = lane >> 2, cc = lane & 3;
    const int r0 = blockIdx.y * 128, c0 = blockIdx.x * 256;
    const float* Ab = A + (size_t)r0 * 512;
    const float* Wb = W + (size_t)c0 * 512;

    const int arow = tid >> 1, acol = (tid & 1) * 8;   // A: 2 float4 / thread
    const int brow = tid;                              // B: 4 float4 / thread

    float4 pa[2], pb[4];
    #pragma unroll
    for (int i = 0; i < 2; i++) pa[i] = *(const float4*)(Ab + (size_t)arow * 512 + acol + i * 4);
    #pragma unroll
    for (int i = 0; i < 4; i++) pb[i] = *(const float4*)(Wb + (size_t)brow * 512 + i * 4);
    #pragma unroll
    for (int i = 0; i < 2; i++) st_tf32_4(&ASP(0, arow, acol + i * 4), pa[i]);
    #pragma unroll
    for (int i = 0; i < 4; i++) st_tf32_4(&BSP(0, brow, i * 4), pb[i]);
    __syncthreads();

    float acc[4][8][4];
    #pragma unroll
    for (int mt = 0; mt < 4; mt++)
        #pragma unroll
        for (int nt = 0; nt < 8; nt++)
            #pragma unroll
            for (int j = 0; j < 4; j++) acc[mt][nt][j] = 0.f;

    for (int kt = 0; kt < 32; kt++) {
        const int cur = kt & 1;
        if (kt < 31) {
            const int kk = (kt + 1) * 16;
            #pragma unroll
            for (int i = 0; i < 2; i++) pa[i] = *(const float4*)(Ab + (size_t)arow * 512 + kk + acol + i * 4);
            #pragma unroll
            for (int i = 0; i < 4; i++) pb[i] = *(const float4*)(Wb + (size_t)brow * 512 + kk + i * 4);
        }
        #pragma unroll
        for (int ks = 0; ks < 2; ks++) {
            const int k0 = ks * 8;
            unsigned af[4][4], bf[8][2];
            #pragma unroll
            for (int mt = 0; mt < 4; mt++) {
                const int rb = wm + mt * 16 + g;
                af[mt][0] = __float_as_uint(ASP(cur, rb,     k0 + cc));
                af[mt][1] = __float_as_uint(ASP(cur, rb + 8, k0 + cc));
                af[mt][2] = __float_as_uint(ASP(cur, rb,     k0 + cc + 4));
                af[mt][3] = __float_as_uint(ASP(cur, rb + 8, k0 + cc + 4));
            }
            #pragma unroll
            for (int nt = 0; nt < 8; nt++) {
                const int nb = wn + nt * 8 + g;
                bf[nt][0] = __float_as_uint(BSP(cur, nb, k0 + cc));
                bf[nt][1] = __float_as_uint(BSP(cur, nb, k0 + cc + 4));
            }
            #pragma unroll
            for (int mt = 0; mt < 4; mt++)
                #pragma unroll
                for (int nt = 0; nt < 8; nt++) mma8(acc[mt][nt], af[mt], bf[nt]);
        }
        if (kt < 31) {
            const int nb = cur ^ 1;
            #pragma unroll
            for (int i = 0; i < 2; i++) st_tf32_4(&ASP(nb, arow, acol + i * 4), pa[i]);
            #pragma unroll
            for (int i = 0; i < 4; i++) st_tf32_4(&BSP(nb, brow, i * 4), pb[i]);
        }
        __syncthreads();
    }

    // epilogue: 4 passes of 64 cols through stage, coalesced store + bias
    float* stage = SM;   // 128*68 floats
    const int rr = tid >> 1, half = tid & 1;
    #pragma unroll
    for (int p = 0; p < 4; p++) {
        if ((warp >> 1) == p) {
            #pragma unroll
            for (int mt = 0; mt < 4; mt++)
                #pragma unroll
                for (int nt = 0; nt < 8; nt++) {
                    const int row = wm + mt * 16 + g, col = nt * 8 + cc * 2;
                    *(float2*)&stage[row * 68 + col]       = make_float2(acc[mt][nt][0], acc[mt][nt][1]);
                    *(float2*)&stage[(row + 8) * 68 + col] = make_float2(acc[mt][nt][2], acc[mt][nt][3]);
                }
        }
        __syncthreads();
        const int cg = c0 + p * 64 + half * 32;
        #pragma unroll
        for (int i = 0; i < 8; i++) {
            float4 v = *(float4*)&stage[rr * 68 + half * 32 + i * 4];
            if (bias) {
                v.x += bias[cg + i * 4];     v.y += bias[cg + i * 4 + 1];
                v.z += bias[cg + i * 4 + 2]; v.w += bias[cg + i * 4 + 3];
            }
            *(float4*)(C + (size_t)(r0 + rr) * GJ + cg + i * 4) = v;
        }
        __syncthreads();
    }
#undef ASP
#undef BSP
}

// ---------------- persistent level-scan kernel (tf32 mma recurrent GEMM) ----
// BM=128, BN=256, BK=16, 256 threads (8 warps: 2m x 4n), warp tile 64x64.
__global__ __launch_bounds__(256) void scan_levels(
    float* __restrict__ out,
    const int* __restrict__ nc,
    const float* __restrict__ wr,    // (1536, 512)
    const float* __restrict__ ur,    // (1536, 512)
    const float* __restrict__ wo)    // (3, 512, 8)
{
    __shared__ float SM[15360];
    __shared__ int rowoff[128];
    __shared__ int rowgid[128];
#define ASP(b,r,k) SM[(b)*2560 + (r)*20 + (k)]
#define BSP(b,r,k) SM[5120 + (b)*5120 + (r)*20 + (k)]

    const int tid = threadIdx.x, lane = tid & 31, warp = tid >> 5;
    const int wm = (warp & 1) * 64, wn = (warp >> 1) * 64;
    const int g = lane >> 2, cc = lane & 3;
    const int arow = tid >> 1, acol = (tid & 1) * 8;
    const int brow = tid;
    const unsigned ncta = gridDim.x;

    const unsigned base = *(volatile unsigned*)&g_ggen;
    unsigned nbar = 0;
    const int maxlev = g_maxlev;

    for (int lev = 0; lev <= maxlev; lev++) {
        const int s = g_lstart[lev];
        const int R = g_lstart[lev + 1] - s;
        const int nrb = (R + 127) >> 7;
        const int units = nrb * 12;   // 3072/256 col blocks

        // ---------------- phase 1: recurrent GEMM + pooling ----------------
        for (int u = blockIdx.x; u < units; u += ncta) {
            const int rb = u / 12;
            const int cb = u - rb * 12;
            const int row0 = rb << 7;

            if (tid < 128) {
                int r = row0 + tid;
                int off = -1, gid = -1;
                if (r < R) {
                    gid = g_nodelist[s + r];
                    int b = gid >> 9, t = gid & 511;
                    int par = nc[(b << 9) + t];
                    if (t > 0 && par < t) off = ((b << 9) + par) << 9;
                }
                rowgid[tid] = gid;
                rowoff[tid] = off;
            }
            __syncthreads();

            const int aoff = rowoff[arow];
            const float* Wb = (cb < 6)
                ? (wr + ((size_t)cb << 17))
                : (ur + ((size_t)(cb - 6) << 17));

            float4 pa[2], pb[4];
            #pragma unroll
            for (int i = 0; i < 2; i++)
                pa[i] = (aoff >= 0) ? *(const float4*)(out + (size_t)aoff + acol + i * 4)
                                    : make_float4(0.f, 0.f, 0.f, 0.f);
            #pragma unroll
            for (int i = 0; i < 4; i++)
                pb[i] = *(const float4*)(Wb + (size_t)brow * 512 + i * 4);
            #pragma unroll
            for (int i = 0; i < 2; i++) st_tf32_4(&ASP(0, arow, acol + i * 4), pa[i]);
            #pragma unroll
            for (int i = 0; i < 4; i++) st_tf32_4(&BSP(0, brow, i * 4), pb[i]);
            __syncthreads();

            float acc[4][8][4];
            #pragma unroll
            for (int mt = 0; mt < 4; mt++)
                #pragma unroll
                for (int nt = 0; nt < 8; nt++)
                    #pragma unroll
                    for (int j = 0; j < 4; j++) acc[mt][nt][j] = 0.f;

            for (int kt = 0; kt < 32; kt++) {
                const int cur = kt & 1;
                if (kt < 31) {
                    const int kk = (kt + 1) * 16;
                    #pragma unroll
                    for (int i = 0; i < 2; i++)
                        pa[i] = (aoff >= 0) ? *(const float4*)(out + (size_t)aoff + kk + acol + i * 4)
                                            : make_float4(0.f, 0.f, 0.f, 0.f);
                    #pragma unroll
                    for (int i = 0; i < 4; i++)
                        pb[i] = *(const float4*)(Wb + (size_t)brow * 512 + kk + i * 4);
                }
                #pragma unroll
                for (int ks = 0; ks < 2; ks++) {
                    const int k0 = ks * 8;
                    unsigned af[4][4], bf[8][2];
                    #pragma unroll
                    for (int mt = 0; mt < 4; mt++) {
                        const int rb2 = wm + mt * 16 + g;
                        af[mt][0] = __float_as_uint(ASP(cur, rb2,     k0 + cc));
                        af[mt][1] = __float_as_uint(ASP(cur, rb2 + 8, k0 + cc));
                        af[mt][2] = __float_as_uint(ASP(cur, rb2,     k0 + cc + 4));
                        af[mt][3] = __float_as_uint(ASP(cur, rb2 + 8, k0 + cc + 4));
                    }
                    #pragma unroll
                    for (int nt = 0; nt < 8; nt++) {
                        const int nb2 = wn + nt * 8 + g;
                        bf[nt][0] = __float_as_uint(BSP(cur, nb2, k0 + cc));
                        bf[nt][1] = __float_as_uint(BSP(cur, nb2, k0 + cc + 4));
                    }
                    #pragma unroll
                    for (int mt = 0; mt < 4; mt++)
                        #pragma unroll
                        for (int nt = 0; nt < 8; nt++) mma8(acc[mt][nt], af[mt], bf[nt]);
                }
                if (kt < 31) {
                    const int nb = cur ^ 1;
                    #pragma unroll
                    for (int i = 0; i < 2; i++) st_tf32_4(&ASP(nb, arow, acol + i * 4), pa[i]);
                    #pragma unroll
                    for (int i = 0; i < 4; i++) st_tf32_4(&BSP(nb, brow, i * 4), pb[i]);
                }
                __syncthreads();
            }

            // epilogue: 4 passes of 64 cols through stage
            float* stage = SM;
            const int rr = tid >> 1, half = tid & 1;
            const int gid = rowgid[rr];
            #pragma unroll
            for (int p = 0; p < 4; p++) {
                if ((warp >> 1) == p) {
                    #pragma unroll
                    for (int mt = 0; mt < 4; mt++)
                        #pragma unroll
                        for (int nt = 0; nt < 8; nt++) {
                            const int row = wm + mt * 16 + g, col = nt * 8 + cc * 2;
                            *(float2*)&stage[row * 68 + col]       = make_float2(acc[mt][nt][0], acc[mt][nt][1]);
                            *(float2*)&stage[(row + 8) * 68 + col] = make_float2(acc[mt][nt][2], acc[mt][nt][3]);
                        }
                }
                __syncthreads();

                if (cb < 6) {
                    // bilinear pooling: this 64-col slab = pool group cb*4+p
                    float v = 0.f;
                    if (gid >= 0) {
                        const float* lwp = g_LW + (size_t)gid * GJ + (cb << 8) + p * 64 + half * 32;
                        #pragma unroll
                        for (int i = 0; i < 8; i++) {
                            float4 l4 = *(const float4*)(lwp + i * 4);
                            float4 c4 = *(float4*)&stage[rr * 68 + half * 32 + i * 4];
                            v += c4.x * l4.x + c4.y * l4.y + c4.z * l4.z + c4.w * l4.w;
                        }
                    }
                    v += __shfl_xor_sync(0xffffffffu, v, 1);
                    if (half == 0 && gid >= 0) g_pooled[(size_t)gid * 24 + cb * 4 + p] = v;
                } else {
                    if (gid >= 0) {
                        const int j0 = ((cb - 6) << 8) + p * 64 + half * 32;
                        #pragma unroll
                        for (int i = 0; i < 8; i++) {
                            float4 c4 = *(float4*)&stage[rr * 68 + half * 32 + i * 4];
                            *(float4*)(g_rlin + (size_t)gid * GJ + j0 + i * 4) = c4;
                        }
                    }
                }
                __syncthreads();
            }
        }

        // grid barrier ------------------------------------------------------
        nbar++;
        __syncthreads();
        if (tid == 0) {
            __threadfence();
            unsigned arrived = atomicAdd(&g_gcnt, 1u);
            if (arrived == ncta - 1u) {
                g_gcnt = 0;
                __threadfence();
                atomicAdd(&g_ggen, 1u);
            } else {
                while ((*(volatile unsigned*)&g_ggen) - base < nbar) { }
            }
            __threadfence();
        }
        __syncthreads();

        // ---------------- phase 2: gate assembly + activations --------------
        for (int r2 = blockIdx.x; r2 < R; r2 += ncta) {
            const int gid = g_nodelist[s + r2];
            const int b = gid >> 9, t = gid & 511;
            const int par = nc[(b << 9) + t];
            const bool hasp = (t > 0 && par < t);
            const size_t pbase = hasp ? ((size_t)((b << 9) + par) << 9) : 0;
            const size_t ubase = (size_t)gid * GJ;
            const size_t obase = (size_t)gid << 9;

            float pl[24];
            {
                const float4* pp = (const float4*)(g_pooled + (size_t)gid * 24);
                #pragma unroll
                for (int i = 0; i < 6; i++) {
                    float4 q = pp[i];
                    pl[i * 4] = q.x; pl[i * 4 + 1] = q.y; pl[i * 4 + 2] = q.z; pl[i * 4 + 3] = q.w;
                }
            }

            #pragma unroll
            for (int hh = 0; hh < 2; hh++) {
                const int h = (hh << 8) + tid;
                float gate[3];
                #pragma unroll
                for (int gg = 0; gg < 3; gg++) {
                    float sg = g_Ubuf[ubase + (gg << 9) + h] + g_rlin[ubase + (gg << 9) + h];
                    const float* wop = wo + (((size_t)(gg << 9) + h) << 3);
                    float4 w0 = *(const float4*)(wop);
                    float4 w1 = *(const float4*)(wop + 4);
                    sg += pl[(gg << 3) + 0] * w0.x + pl[(gg << 3) + 1] * w0.y
                        + pl[(gg << 3) + 2] * w0.z + pl[(gg << 3) + 3] * w0.w
                        + pl[(gg << 3) + 4] * w1.x + pl[(gg << 3) + 5] * w1.y
                        + pl[(gg << 3) + 6] * w1.z + pl[(gg << 3) + 7] * w1.w;
                    gate[gg] = sg;
                }
                const float f = 1.f / (1.f + expf(-gate[0]));
                const float o = 1.f / (1.f + expf(-gate[1]));
                const float z = tanhf(gate[2]);
                const float pc = hasp ? g_cbuf[pbase + h] : 0.f;
                const float c = pc * f + (1.f - f) * z;
                g_cbuf[obase + h] = c;
                out[obase + h] = o * tanhf(c);
            }
        }

        // grid barrier ------------------------------------------------------
        nbar++;
        __syncthreads();
        if (tid == 0) {
            __threadfence();
            unsigned arrived = atomicAdd(&g_gcnt, 1u);
            if (arrived == ncta - 1u) {
                g_gcnt = 0;
                __threadfence();
                atomicAdd(&g_ggen, 1u);
            } else {
                while ((*(volatile unsigned*)&g_ggen) - base < nbar) { }
            }
            __threadfence();
        }
        __syncthreads();
    }
#undef ASP
#undef BSP
}

// ---------------------------- launch ----------------------------------------
extern "C" void kernel_launch(void* const* d_in, const int* in_sizes, int n_in,
                              void* d_out, int out_size)
{
    (void)in_sizes; (void)n_in; (void)out_size;
    const float* emb  = (const float*)d_in[0];
    const int*   nc   = (const int*)d_in[1];
    // d_in[2] = node_mask (unused by reference)
    const float* wl   = (const float*)d_in[3];
    const float* wr   = (const float*)d_in[4];
    const float* wo   = (const float*)d_in[5];
    const float* ul   = (const float*)d_in[6];
    const float* ur   = (const float*)d_in[7];
    const float* bias = (const float*)d_in[8];
    float* out = (float*)d_out;

    // launch order chosen so ncu (-s 5 -c 1) captures scan_levels (index 5)
    build_depth<<<128, 32>>>(nc);       // 0
    prefix_levels<<<1, 1>>>();          // 1 (also re-zeros g_lcount)
    scatter_levels<<<128, 512>>>();     // 2

    dim3 gp(GJ / 256, MROWS / 128);     // (6, 512)
    gemm_pre<<<gp, 256>>>(emb, ul, bias, 0);    // 3
    gemm_pre<<<gp, 256>>>(emb, wl, nullptr, 1); // 4

    scan_levels<<<NCTA, 256>>>(out, nc, wr, ur, wo);  // 5
}

// round 6
// speedup vs baseline: 1.0656x; 1.0656x over previous
#include <cuda_runtime.h>
#include <math.h>

// Problem constants
#define Bsz   128
#define Nn    512
#define GJ    1536          // 3*512 gate columns
#define MROWS (Bsz*Nn)      // 65536
#define NCTA  148           // persistent grid (1 CTA/SM guaranteed resident)

// ---------------- device scratch (allocation-free) ---------------------------
__device__ float g_Ubuf[(size_t)MROWS * GJ];   // emb@ul^T + bias
__device__ float g_LW  [(size_t)MROWS * GJ];   // emb@wl^T
__device__ float g_rlin[(size_t)MROWS * GJ];   // ph@ur^T
__device__ float g_cbuf[(size_t)MROWS * 512];  // cell state
__device__ float g_pooled[(size_t)MROWS * 24]; // pooled bilinear
__device__ float g_zero[512];                  // all-zero row for invalid gathers

__device__ int g_level[MROWS];
__device__ int g_lcount[512];
__device__ int g_lstart[513];
__device__ int g_lcur[512];
__device__ int g_nodelist[MROWS];
__device__ int g_maxlev;

__device__ unsigned g_gcnt = 0;
__device__ unsigned g_ggen = 0;

// ---------------- tf32 / cp.async helpers ------------------------------------
__device__ __forceinline__ unsigned f2t(float x) {
    unsigned u; asm("cvt.rna.tf32.f32 %0, %1;" : "=r"(u) : "f"(x)); return u;
}
__device__ __forceinline__ void mma8(float* c, const unsigned* a, const unsigned* b) {
    asm volatile(
        "mma.sync.aligned.m16n8k8.row.col.f32.tf32.tf32.f32 "
        "{%0,%1,%2,%3},{%4,%5,%6,%7},{%8,%9},{%0,%1,%2,%3};"
        : "+f"(c[0]), "+f"(c[1]), "+f"(c[2]), "+f"(c[3])
        : "r"(a[0]), "r"(a[1]), "r"(a[2]), "r"(a[3]), "r"(b[0]), "r"(b[1]));
}
__device__ __forceinline__ void cpa16(unsigned dst, const float* src) {
    asm volatile("cp.async.cg.shared.global [%0], [%1], 16;" :: "r"(dst), "l"(src));
}
#define CP_COMMIT() asm volatile("cp.async.commit_group;")
#define CP_WAIT1()  asm volatile("cp.async.wait_group 1;")

// ---------------- level metadata kernels ------------------------------------
__global__ void build_depth(const int* __restrict__ nc) {
    __shared__ int spar[512];
    __shared__ unsigned short dep[512];
    const int b = blockIdx.x;
    for (int t = threadIdx.x; t < 512; t += 32) spar[t] = nc[b * 512 + t];
    __syncthreads();
    if (threadIdx.x == 0) {
        for (int t = 0; t < 512; t++) {
            int par = spar[t];
            dep[t] = (t > 0 && par < t) ? (unsigned short)(dep[par] + 1) : 0;
        }
    }
    __syncthreads();
    for (int t = threadIdx.x; t < 512; t += 32) {
        int lv = dep[t];
        g_level[b * 512 + t] = lv;
        atomicAdd(&g_lcount[lv], 1);
    }
}

__global__ void prefix_levels() {
    int sum = 0, mx = 0;
    for (int l = 0; l < 512; l++) {
        g_lstart[l] = sum;
        g_lcur[l]   = sum;
        if (g_lcount[l] > 0) mx = l;
        sum += g_lcount[l];
        g_lcount[l] = 0;   // re-zero for next replay
    }
    g_lstart[512] = sum;
    g_maxlev = mx;
}

__global__ void scatter_levels() {
    int i = blockIdx.x * 512 + threadIdx.x;
    if (i < MROWS) {
        int pos = atomicAdd(&g_lcur[g_level[i]], 1);
        g_nodelist[pos] = i;
    }
}

// ---------------- precompute GEMM (tf32 mma + cp.async) ----------------------
// C[M x 1536] = A[M x 512] @ W[1536 x 512]^T (+bias)
// BM=128, BN=128, BK=16, 3 stages, 256 threads (8 warps 2m x 4n), warp 64x32.
__global__ __launch_bounds__(256, 2) void gemm_pre(
    const float* __restrict__ A, const float* __restrict__ W,
    const float* __restrict__ bias, int sel)
{
    __shared__ __align__(16) float SM[15360];  // 3 stages x (As 128x20 + Bs 128x20)

    float* C = sel ? g_LW : g_Ubuf;

    const int tid = threadIdx.x, lane = tid & 31, warp = tid >> 5;
    const int wm = (warp & 1) * 64, wn = (warp >> 1) * 32;
    const int g = lane >> 2, cc = lane & 3;
    const int r0 = blockIdx.y * 128, c0 = blockIdx.x * 128;
    const float* Ab = A + (size_t)r0 * 512;
    const float* Wb = W + (size_t)c0 * 512;

    const int arow = tid >> 1, acol = (tid & 1) * 8;
    const unsigned sb = (unsigned)__cvta_generic_to_shared(SM);

    auto issue = [&](int s, int kt) {
        const float* as_ = Ab + (size_t)arow * 512 + kt * 16 + acol;
        const float* bs_ = Wb + (size_t)arow * 512 + kt * 16 + acol;
        unsigned ad = sb + (unsigned)(s * 5120 + arow * 20 + acol) * 4u;
        unsigned bd = sb + (unsigned)(s * 5120 + 2560 + arow * 20 + acol) * 4u;
        cpa16(ad, as_); cpa16(ad + 16, as_ + 4);
        cpa16(bd, bs_); cpa16(bd + 16, bs_ + 4);
    };

    issue(0, 0); CP_COMMIT();
    issue(1, 1); CP_COMMIT();

    float acc[4][4][4];
    #pragma unroll
    for (int mt = 0; mt < 4; mt++)
        #pragma unroll
        for (int nt = 0; nt < 4; nt++)
            #pragma unroll
            for (int j = 0; j < 4; j++) acc[mt][nt][j] = 0.f;

    for (int kt = 0; kt < 32; kt++) {
        CP_WAIT1();
        __syncthreads();
        if (kt + 2 < 32) issue((kt + 2) % 3, kt + 2);
        CP_COMMIT();

        const float* Asb = SM + (kt % 3) * 5120;
        const float* Bsb = Asb + 2560;
        #pragma unroll
        for (int ks = 0; ks < 2; ks++) {
            const int k0 = ks * 8;
            unsigned af[4][4], bf[4][2];
            #pragma unroll
            for (int mt = 0; mt < 4; mt++) {
                const int rb = wm + mt * 16 + g;
                af[mt][0] = f2t(Asb[rb * 20 + k0 + cc]);
                af[mt][1] = f2t(Asb[(rb + 8) * 20 + k0 + cc]);
                af[mt][2] = f2t(Asb[rb * 20 + k0 + cc + 4]);
                af[mt][3] = f2t(Asb[(rb + 8) * 20 + k0 + cc + 4]);
            }
            #pragma unroll
            for (int nt = 0; nt < 4; nt++) {
                const int nb = wn + nt * 8 + g;
                bf[nt][0] = f2t(Bsb[nb * 20 + k0 + cc]);
                bf[nt][1] = f2t(Bsb[nb * 20 + k0 + cc + 4]);
            }
            #pragma unroll
            for (int mt = 0; mt < 4; mt++)
                #pragma unroll
                for (int nt = 0; nt < 4; nt++) mma8(acc[mt][nt], af[mt], bf[nt]);
        }
    }
    __syncthreads();

    // epilogue: 2 passes of 64 cols staged through smem, coalesced store + bias
    float* stage = SM;   // 128*68 floats
    const int rr = tid >> 1, half = tid & 1;
    #pragma unroll
    for (int p = 0; p < 2; p++) {
        if ((warp >> 2) == p) {
            #pragma unroll
            for (int mt = 0; mt < 4; mt++)
                #pragma unroll
                for (int nt = 0; nt < 4; nt++) {
                    const int row = wm + mt * 16 + g, col = wn - p * 64 + nt * 8 + cc * 2;
                    *(float2*)&stage[row * 68 + col]       = make_float2(acc[mt][nt][0], acc[mt][nt][1]);
                    *(float2*)&stage[(row + 8) * 68 + col] = make_float2(acc[mt][nt][2], acc[mt][nt][3]);
                }
        }
        __syncthreads();
        const int cg = c0 + p * 64 + half * 32;
        #pragma unroll
        for (int i = 0; i < 8; i++) {
            float4 v = *(float4*)&stage[rr * 68 + half * 32 + i * 4];
            if (bias) {
                v.x += bias[cg + i * 4];     v.y += bias[cg + i * 4 + 1];
                v.z += bias[cg + i * 4 + 2]; v.w += bias[cg + i * 4 + 3];
            }
            *(float4*)(C + (size_t)(r0 + rr) * GJ + cg + i * 4) = v;
        }
        __syncthreads();
    }
}

// ---------------- persistent level-scan kernel (tf32 mma + cp.async) ---------
// BM=128, BN=256, BK=16, 3 stages, 256 threads (8 warps 2m x 4n), warp 64x64.
__global__ __launch_bounds__(256) void scan_levels(
    float* __restrict__ out,
    const int* __restrict__ nc,
    const float* __restrict__ wr,    // (1536, 512)
    const float* __restrict__ ur,    // (1536, 512)
    const float* __restrict__ wo)    // (3, 512, 8)
{
    __shared__ __align__(16) float SM[23040];  // 3 stages x (As 128x20 + Bs 256x20)
    __shared__ int rowoff[128];
    __shared__ int rowgid[128];

    const int tid = threadIdx.x, lane = tid & 31, warp = tid >> 5;
    const int wm = (warp & 1) * 64, wn = (warp >> 1) * 64;
    const int g = lane >> 2, cc = lane & 3;
    const int arow = tid >> 1, acol = (tid & 1) * 8;
    const unsigned ncta = gridDim.x;
    const unsigned sb = (unsigned)__cvta_generic_to_shared(SM);

    const unsigned base = *(volatile unsigned*)&g_ggen;
    unsigned nbar = 0;
    const int maxlev = g_maxlev;

    for (int lev = 0; lev <= maxlev; lev++) {
        const int s = g_lstart[lev];
        const int R = g_lstart[lev + 1] - s;
        const int nrb = (R + 127) >> 7;
        const int units = nrb * 12;   // 3072/256 col blocks

        // ---------------- phase 1: recurrent GEMM + pooling ----------------
        for (int u = blockIdx.x; u < units; u += ncta) {
            const int rb = u / 12;
            const int cb = u - rb * 12;
            const int row0 = rb << 7;

            if (tid < 128) {
                int r = row0 + tid;
                int off = -1, gid = -1;
                if (r < R) {
                    gid = g_nodelist[s + r];
                    int b = gid >> 9, t = gid & 511;
                    int par = nc[(b << 9) + t];
                    if (t > 0 && par < t) off = ((b << 9) + par) << 9;
                }
                rowgid[tid] = gid;
                rowoff[tid] = off;
            }
            __syncthreads();

            const int aoff = rowoff[arow];
            const float* abase = (aoff >= 0) ? (out + (size_t)aoff) : g_zero;
            const float* Wb = (cb < 6)
                ? (wr + ((size_t)cb << 17))
                : (ur + ((size_t)(cb - 6) << 17));
            const float* brow_ptr = Wb + (size_t)tid * 512;

            auto issue = [&](int st, int kt) {
                const float* as_ = abase + kt * 16 + acol;
                unsigned ad = sb + (unsigned)(st * 7680 + arow * 20 + acol) * 4u;
                cpa16(ad, as_); cpa16(ad + 16, as_ + 4);
                const float* bs_ = brow_ptr + kt * 16;
                unsigned bd = sb + (unsigned)(st * 7680 + 2560 + tid * 20) * 4u;
                cpa16(bd, bs_);      cpa16(bd + 16, bs_ + 4);
                cpa16(bd + 32, bs_ + 8); cpa16(bd + 48, bs_ + 12);
            };

            issue(0, 0); CP_COMMIT();
            issue(1, 1); CP_COMMIT();

            float acc[4][8][4];
            #pragma unroll
            for (int mt = 0; mt < 4; mt++)
                #pragma unroll
                for (int nt = 0; nt < 8; nt++)
                    #pragma unroll
                    for (int j = 0; j < 4; j++) acc[mt][nt][j] = 0.f;

            for (int kt = 0; kt < 32; kt++) {
                CP_WAIT1();
                __syncthreads();
                if (kt + 2 < 32) issue((kt + 2) % 3, kt + 2);
                CP_COMMIT();

                const float* Asb = SM + (kt % 3) * 7680;
                const float* Bsb = Asb + 2560;
                #pragma unroll
                for (int ks = 0; ks < 2; ks++) {
                    const int k0 = ks * 8;
                    unsigned af[4][4], bf[8][2];
                    #pragma unroll
                    for (int mt = 0; mt < 4; mt++) {
                        const int rb2 = wm + mt * 16 + g;
                        af[mt][0] = f2t(Asb[rb2 * 20 + k0 + cc]);
                        af[mt][1] = f2t(Asb[(rb2 + 8) * 20 + k0 + cc]);
                        af[mt][2] = f2t(Asb[rb2 * 20 + k0 + cc + 4]);
                        af[mt][3] = f2t(Asb[(rb2 + 8) * 20 + k0 + cc + 4]);
                    }
                    #pragma unroll
                    for (int nt = 0; nt < 8; nt++) {
                        const int nb2 = wn + nt * 8 + g;
                        bf[nt][0] = f2t(Bsb[nb2 * 20 + k0 + cc]);
                        bf[nt][1] = f2t(Bsb[nb2 * 20 + k0 + cc + 4]);
                    }
                    #pragma unroll
                    for (int mt = 0; mt < 4; mt++)
                        #pragma unroll
                        for (int nt = 0; nt < 8; nt++) mma8(acc[mt][nt], af[mt], bf[nt]);
                }
            }
            __syncthreads();

            // epilogue: 4 passes of 64 cols through stage (reuse SM)
            float* stage = SM;
            const int rr = tid >> 1, half = tid & 1;
            const int gid = rowgid[rr];
            #pragma unroll
            for (int p = 0; p < 4; p++) {
                if ((warp >> 1) == p) {
                    #pragma unroll
                    for (int mt = 0; mt < 4; mt++)
                        #pragma unroll
                        for (int nt = 0; nt < 8; nt++) {
                            const int row = wm + mt * 16 + g, col = nt * 8 + cc * 2;
                            *(float2*)&stage[row * 68 + col]       = make_float2(acc[mt][nt][0], acc[mt][nt][1]);
                            *(float2*)&stage[(row + 8) * 68 + col] = make_float2(acc[mt][nt][2], acc[mt][nt][3]);
                        }
                }
                __syncthreads();

                if (cb < 6) {
                    // bilinear pooling: this 64-col slab = pool group cb*4+p
                    float v = 0.f;
                    if (gid >= 0) {
                        const float* lwp = g_LW + (size_t)gid * GJ + (cb << 8) + p * 64 + half * 32;
                        #pragma unroll
                        for (int i = 0; i < 8; i++) {
                            float4 l4 = *(const float4*)(lwp + i * 4);
                            float4 c4 = *(float4*)&stage[rr * 68 + half * 32 + i * 4];
                            v += c4.x * l4.x + c4.y * l4.y + c4.z * l4.z + c4.w * l4.w;
                        }
                    }
                    v += __shfl_xor_sync(0xffffffffu, v, 1);
                    if (half == 0 && gid >= 0) g_pooled[(size_t)gid * 24 + cb * 4 + p] = v;
                } else {
                    if (gid >= 0) {
                        const int j0 = ((cb - 6) << 8) + p * 64 + half * 32;
                        #pragma unroll
                        for (int i = 0; i < 8; i++) {
                            float4 c4 = *(float4*)&stage[rr * 68 + half * 32 + i * 4];
                            *(float4*)(g_rlin + (size_t)gid * GJ + j0 + i * 4) = c4;
                        }
                    }
                }
                __syncthreads();
            }
        }

        // grid barrier ------------------------------------------------------
        nbar++;
        __syncthreads();
        if (tid == 0) {
            __threadfence();
            unsigned arrived = atomicAdd(&g_gcnt, 1u);
            if (arrived == ncta - 1u) {
                g_gcnt = 0;
                __threadfence();
                atomicAdd(&g_ggen, 1u);
            } else {
                while ((*(volatile unsigned*)&g_ggen) - base < nbar) { }
            }
            __threadfence();
        }
        __syncthreads();

        // ---------------- phase 2: gate assembly + activations --------------
        for (int r2 = blockIdx.x; r2 < R; r2 += ncta) {
            const int gid = g_nodelist[s + r2];
            const int b = gid >> 9, t = gid & 511;
            const int par = nc[(b << 9) + t];
            const bool hasp = (t > 0 && par < t);
            const size_t pbase = hasp ? ((size_t)((b << 9) + par) << 9) : 0;
            const size_t ubase = (size_t)gid * GJ;
            const size_t obase = (size_t)gid << 9;

            float pl[24];
            {
                const float4* pp = (const float4*)(g_pooled + (size_t)gid * 24);
                #pragma unroll
                for (int i = 0; i < 6; i++) {
                    float4 q = pp[i];
                    pl[i * 4] = q.x; pl[i * 4 + 1] = q.y; pl[i * 4 + 2] = q.z; pl[i * 4 + 3] = q.w;
                }
            }

            #pragma unroll
            for (int hh = 0; hh < 2; hh++) {
                const int h = (hh << 8) + tid;
                float gate[3];
                #pragma unroll
                for (int gg = 0; gg < 3; gg++) {
                    float sg = g_Ubuf[ubase + (gg << 9) + h] + g_rlin[ubase + (gg << 9) + h];
                    const float* wop = wo + (((size_t)(gg << 9) + h) << 3);
                    float4 w0 = *(const float4*)(wop);
                    float4 w1 = *(const float4*)(wop + 4);
                    sg += pl[(gg << 3) + 0] * w0.x + pl[(gg << 3) + 1] * w0.y
                        + pl[(gg << 3) + 2] * w0.z + pl[(gg << 3) + 3] * w0.w
                        + pl[(gg << 3) + 4] * w1.x + pl[(gg << 3) + 5] * w1.y
                        + pl[(gg << 3) + 6] * w1.z + pl[(gg << 3) + 7] * w1.w;
                    gate[gg] = sg;
                }
                const float f = 1.f / (1.f + expf(-gate[0]));
                const float o = 1.f / (1.f + expf(-gate[1]));
                const float z = tanhf(gate[2]);
                const float pc = hasp ? g_cbuf[pbase + h] : 0.f;
                const float c = pc * f + (1.f - f) * z;
                g_cbuf[obase + h] = c;
                out[obase + h] = o * tanhf(c);
            }
        }

        // grid barrier ------------------------------------------------------
        nbar++;
        __syncthreads();
        if (tid == 0) {
            __threadfence();
            unsigned arrived = atomicAdd(&g_gcnt, 1u);
            if (arrived == ncta - 1u) {
                g_gcnt = 0;
                __threadfence();
                atomicAdd(&g_ggen, 1u);
            } else {
                while ((*(volatile unsigned*)&g_ggen) - base < nbar) { }
            }
            __threadfence();
        }
        __syncthreads();
    }
}

// ---------------------------- launch ----------------------------------------
extern "C" void kernel_launch(void* const* d_in, const int* in_sizes, int n_in,
                              void* d_out, int out_size)
{
    (void)in_sizes; (void)n_in; (void)out_size;
    const float* emb  = (const float*)d_in[0];
    const int*   nc   = (const int*)d_in[1];
    // d_in[2] = node_mask (unused by reference)
    const float* wl   = (const float*)d_in[3];
    const float* wr   = (const float*)d_in[4];
    const float* wo   = (const float*)d_in[5];
    const float* ul   = (const float*)d_in[6];
    const float* ur   = (const float*)d_in[7];
    const float* bias = (const float*)d_in[8];
    float* out = (float*)d_out;

    // launch order chosen so ncu (-s 5 -c 1) captures scan_levels (index 5)
    build_depth<<<128, 32>>>(nc);       // 0
    prefix_levels<<<1, 1>>>();          // 1 (also re-zeros g_lcount)
    scatter_levels<<<128, 512>>>();     // 2

    dim3 gp(GJ / 128, MROWS / 128);     // (12, 512)
    gemm_pre<<<gp, 256>>>(emb, ul, bias, 0);    // 3
    gemm_pre<<<gp, 256>>>(emb, wl, nullptr, 1); // 4

    scan_levels<<<NCTA, 256>>>(out, nc, wr, ur, wo);  // 5
}

// round 7
// speedup vs baseline: 1.6027x; 1.5040x over previous
#include <cuda_runtime.h>
#include <cuda_fp16.h>
#include <math.h>

// Problem constants
#define Bsz   128
#define Nn    512
#define GJ    1536          // 3*512 gate columns
#define MROWS (Bsz*Nn)      // 65536
#define NCTA  148           // persistent grid (1 CTA/SM guaranteed resident)
#define NWELEM 786432       // elements per weight matrix (1536*512)

// ---------------- device scratch (allocation-free) ---------------------------
__device__ float  g_Ubuf[(size_t)MROWS * GJ];   // emb@ul^T + bias
__device__ float  g_LW  [(size_t)MROWS * GJ];   // emb@wl^T
__device__ float  g_rlin[(size_t)MROWS * GJ];   // ph@ur^T
__device__ float  g_cbuf[(size_t)MROWS * 512];  // cell state
__device__ float  g_pooled[(size_t)MROWS * 24]; // pooled bilinear
__device__ __half g_embH[(size_t)MROWS * 512];  // fp16 emb
__device__ __half g_hH  [(size_t)MROWS * 512];  // fp16 h (scan A operand)
__device__ __half g_wH  [4 * NWELEM];           // fp16 weights: ul, wl, wr, ur
__device__ __half g_zeroH[512];                 // zero row

__device__ int g_level[MROWS];
__device__ int g_lcount[512];
__device__ int g_lstart[513];
__device__ int g_lcur[512];
__device__ int g_nodelist[MROWS];
__device__ int g_maxlev;

__device__ unsigned g_gcnt = 0;
__device__ unsigned g_ggen = 0;

// ---------------- mma / cp.async helpers -------------------------------------
__device__ __forceinline__ void mma16(float* c, const unsigned* a, const unsigned* b) {
    asm volatile(
        "mma.sync.aligned.m16n8k16.row.col.f32.f16.f16.f32 "
        "{%0,%1,%2,%3},{%4,%5,%6,%7},{%8,%9},{%0,%1,%2,%3};"
        : "+f"(c[0]), "+f"(c[1]), "+f"(c[2]), "+f"(c[3])
        : "r"(a[0]), "r"(a[1]), "r"(a[2]), "r"(a[3]), "r"(b[0]), "r"(b[1]));
}
__device__ __forceinline__ void cpa16(unsigned dst, const void* src) {
    asm volatile("cp.async.cg.shared.global [%0], [%1], 16;" :: "r"(dst), "l"(src));
}
#define CP_COMMIT() asm volatile("cp.async.commit_group;")
#define CP_WAIT1()  asm volatile("cp.async.wait_group 1;")

__device__ __forceinline__ unsigned ldh2(const __half* p) {
    return *(const unsigned*)p;
}

// ---------------- fp32 -> fp16 conversion (one pass, all GEMM inputs) --------
__global__ void conv_all(const float* __restrict__ emb,
                         const float* __restrict__ ul, const float* __restrict__ wl,
                         const float* __restrict__ wr, const float* __restrict__ ur)
{
    const size_t NE = (size_t)MROWS * 512 / 4;   // emb quarters
    const size_t NW = NWELEM / 4;                // weight quarters
    size_t i = (size_t)blockIdx.x * 256 + threadIdx.x;
    const float* src; __half* dst; size_t q;
    if (i < NE) { src = emb; dst = g_embH; q = i; }
    else {
        size_t j = i - NE;
        if (j >= 4 * NW) return;
        int w = (int)(j / NW); q = j % NW;
        src = (w == 0) ? ul : (w == 1) ? wl : (w == 2) ? wr : ur;
        dst = g_wH + (size_t)w * NWELEM;
    }
    float4 v = ((const float4*)src)[q];
    __half2* d2 = (__half2*)(dst + q * 4);
    d2[0] = __floats2half2_rn(v.x, v.y);
    d2[1] = __floats2half2_rn(v.z, v.w);
}

// ---------------- level metadata kernels ------------------------------------
__global__ void build_depth(const int* __restrict__ nc) {
    __shared__ int spar[512];
    __shared__ unsigned short dep[512];
    const int b = blockIdx.x;
    for (int t = threadIdx.x; t < 512; t += 32) spar[t] = nc[b * 512 + t];
    __syncthreads();
    if (threadIdx.x == 0) {
        for (int t = 0; t < 512; t++) {
            int par = spar[t];
            dep[t] = (t > 0 && par < t) ? (unsigned short)(dep[par] + 1) : 0;
        }
    }
    __syncthreads();
    for (int t = threadIdx.x; t < 512; t += 32) {
        int lv = dep[t];
        g_level[b * 512 + t] = lv;
        atomicAdd(&g_lcount[lv], 1);
    }
}

__global__ void prefix_levels() {
    int sum = 0, mx = 0;
    for (int l = 0; l < 512; l++) {
        g_lstart[l] = sum;
        g_lcur[l]   = sum;
        if (g_lcount[l] > 0) mx = l;
        sum += g_lcount[l];
        g_lcount[l] = 0;   // re-zero for next replay
    }
    g_lstart[512] = sum;
    g_maxlev = mx;
}

__global__ void scatter_levels() {
    int i = blockIdx.x * 512 + threadIdx.x;
    if (i < MROWS) {
        int pos = atomicAdd(&g_lcur[g_level[i]], 1);
        g_nodelist[pos] = i;
    }
}

// ---------------- precompute GEMM (fp16 mma + cp.async) ----------------------
// C[M x 1536] = embH[M x 512] @ W[1536 x 512]^T (+bias). z selects ul/wl.
// BM=128, BN=128, BK=32, 3 stages, 256 threads (8 warps 2m x 4n), warp 64x32.
__global__ __launch_bounds__(256, 2) void gemm_pre(
    const float* __restrict__ bias)
{
    __shared__ __align__(16) __half HSM[30720];  // 3 x (A 128x40 + B 128x40)

    const int sel = blockIdx.z;
    float* C = sel ? g_LW : g_Ubuf;

    const int tid = threadIdx.x, lane = tid & 31, warp = tid >> 5;
    const int wm = (warp & 1) * 64, wn = (warp >> 1) * 32;
    const int g = lane >> 2, cc2 = (lane & 3) * 2;
    const int r0 = blockIdx.y * 128, c0 = blockIdx.x * 128;
    const __half* Ab = g_embH + (size_t)r0 * 512;
    const __half* Wb = g_wH + (size_t)sel * NWELEM + (size_t)c0 * 512;

    const int lrow = tid >> 1, lcol = (tid & 1) * 16;
    const unsigned sb = (unsigned)__cvta_generic_to_shared(HSM);

    auto issue = [&](int s, int kt) {
        const __half* as_ = Ab + (size_t)lrow * 512 + kt * 32 + lcol;
        const __half* bs_ = Wb + (size_t)lrow * 512 + kt * 32 + lcol;
        unsigned ad = sb + (unsigned)(s * 10240 + lrow * 40 + lcol) * 2u;
        unsigned bd = sb + (unsigned)(s * 10240 + 5120 + lrow * 40 + lcol) * 2u;
        cpa16(ad, as_); cpa16(ad + 16, as_ + 8);
        cpa16(bd, bs_); cpa16(bd + 16, bs_ + 8);
    };

    issue(0, 0); CP_COMMIT();
    issue(1, 1); CP_COMMIT();

    float acc[4][4][4];
    #pragma unroll
    for (int mt = 0; mt < 4; mt++)
        #pragma unroll
        for (int nt = 0; nt < 4; nt++)
            #pragma unroll
            for (int j = 0; j < 4; j++) acc[mt][nt][j] = 0.f;

    for (int kt = 0; kt < 16; kt++) {
        CP_WAIT1();
        __syncthreads();
        if (kt + 2 < 16) issue((kt + 2) % 3, kt + 2);
        CP_COMMIT();

        const __half* As = HSM + (kt % 3) * 10240;
        const __half* Bs = As + 5120;
        #pragma unroll
        for (int ks = 0; ks < 2; ks++) {
            const int k0 = ks * 16;
            unsigned af[4][4], bf[4][2];
            #pragma unroll
            for (int mt = 0; mt < 4; mt++) {
                const int rb = wm + mt * 16 + g;
                af[mt][0] = ldh2(&As[rb * 40 + k0 + cc2]);
                af[mt][1] = ldh2(&As[(rb + 8) * 40 + k0 + cc2]);
                af[mt][2] = ldh2(&As[rb * 40 + k0 + cc2 + 8]);
                af[mt][3] = ldh2(&As[(rb + 8) * 40 + k0 + cc2 + 8]);
            }
            #pragma unroll
            for (int nt = 0; nt < 4; nt++) {
                const int nb = wn + nt * 8 + g;
                bf[nt][0] = ldh2(&Bs[nb * 40 + k0 + cc2]);
                bf[nt][1] = ldh2(&Bs[nb * 40 + k0 + cc2 + 8]);
            }
            #pragma unroll
            for (int mt = 0; mt < 4; mt++)
                #pragma unroll
                for (int nt = 0; nt < 4; nt++) mma16(acc[mt][nt], af[mt], bf[nt]);
        }
    }
    __syncthreads();

    // epilogue: 2 passes of 64 cols staged through smem (alias as float)
    float* stage = (float*)HSM;   // 128*68 floats = 34816B <= 61440B
    const int rr = tid >> 1, half = tid & 1;
    const int cc = lane & 3;
    #pragma unroll
    for (int p = 0; p < 2; p++) {
        if ((warp >> 2) == p) {
            #pragma unroll
            for (int mt = 0; mt < 4; mt++)
                #pragma unroll
                for (int nt = 0; nt < 4; nt++) {
                    const int row = wm + mt * 16 + g, col = wn - p * 64 + nt * 8 + cc * 2;
                    *(float2*)&stage[row * 68 + col]       = make_float2(acc[mt][nt][0], acc[mt][nt][1]);
                    *(float2*)&stage[(row + 8) * 68 + col] = make_float2(acc[mt][nt][2], acc[mt][nt][3]);
                }
        }
        __syncthreads();
        const int cg = c0 + p * 64 + half * 32;
        #pragma unroll
        for (int i = 0; i < 8; i++) {
            float4 v = *(float4*)&stage[rr * 68 + half * 32 + i * 4];
            if (sel == 0) {
                v.x += bias[cg + i * 4];     v.y += bias[cg + i * 4 + 1];
                v.z += bias[cg + i * 4 + 2]; v.w += bias[cg + i * 4 + 3];
            }
            *(float4*)(C + (size_t)(r0 + rr) * GJ + cg + i * 4) = v;
        }
        __syncthreads();
    }
}

// ---------------- persistent level-scan kernel (fp16 mma + cp.async) ---------
// BM=128, BN=256, BK=32, 3 stages, 256 threads (8 warps 2m x 4n), warp 64x64.
__global__ __launch_bounds__(256) void scan_levels(
    float* __restrict__ out,
    const int* __restrict__ nc,
    const float* __restrict__ wo)    // (3, 512, 8)
{
    __shared__ __align__(16) __half HSM[46080];  // 3 x (A 128x40 + B 256x40)
    __shared__ int rowoff[128];
    __shared__ int rowgid[128];

    const int tid = threadIdx.x, lane = tid & 31, warp = tid >> 5;
    const int wm = (warp & 1) * 64, wn = (warp >> 1) * 64;
    const int g = lane >> 2, cc2 = (lane & 3) * 2, cc = lane & 3;
    const int arow = tid >> 1, acol = (tid & 1) * 16;
    const unsigned ncta = gridDim.x;
    const unsigned sb = (unsigned)__cvta_generic_to_shared(HSM);
    const __half* wrH = g_wH + 2 * (size_t)NWELEM;
    const __half* urH = g_wH + 3 * (size_t)NWELEM;

    const unsigned base = *(volatile unsigned*)&g_ggen;
    unsigned nbar = 0;
    const int maxlev = g_maxlev;

    for (int lev = 0; lev <= maxlev; lev++) {
        const int s = g_lstart[lev];
        const int R = g_lstart[lev + 1] - s;
        const int nrb = (R + 127) >> 7;
        const int units = nrb * 12;   // 3072/256 col blocks

        // ---------------- phase 1: recurrent GEMM + pooling ----------------
        for (int u = blockIdx.x; u < units; u += ncta) {
            const int rb = u / 12;
            const int cb = u - rb * 12;
            const int row0 = rb << 7;

            if (tid < 128) {
                int r = row0 + tid;
                int off = -1, gid = -1;
                if (r < R) {
                    gid = g_nodelist[s + r];
                    int b = gid >> 9, t = gid & 511;
                    int par = nc[(b << 9) + t];
                    if (t > 0 && par < t) off = ((b << 9) + par) << 9;
                }
                rowgid[tid] = gid;
                rowoff[tid] = off;
            }
            __syncthreads();

            const int aoff = rowoff[arow];
            const __half* abase = (aoff >= 0) ? (g_hH + (size_t)aoff) : g_zeroH;
            const __half* Wb = (cb < 6)
                ? (wrH + (size_t)cb * 131072)
                : (urH + (size_t)(cb - 6) * 131072);
            const __half* brow_ptr = Wb + (size_t)tid * 512;

            auto issue = [&](int st, int kt) {
                const __half* as_ = abase + kt * 32 + acol;
                unsigned ad = sb + (unsigned)(st * 15360 + arow * 40 + acol) * 2u;
                cpa16(ad, as_); cpa16(ad + 16, as_ + 8);
                const __half* bs_ = brow_ptr + kt * 32;
                unsigned bd = sb + (unsigned)(st * 15360 + 5120 + tid * 40) * 2u;
                cpa16(bd, bs_);      cpa16(bd + 16, bs_ + 8);
                cpa16(bd + 32, bs_ + 16); cpa16(bd + 48, bs_ + 24);
            };

            issue(0, 0); CP_COMMIT();
            issue(1, 1); CP_COMMIT();

            float acc[4][8][4];
            #pragma unroll
            for (int mt = 0; mt < 4; mt++)
                #pragma unroll
                for (int nt = 0; nt < 8; nt++)
                    #pragma unroll
                    for (int j = 0; j < 4; j++) acc[mt][nt][j] = 0.f;

            for (int kt = 0; kt < 16; kt++) {
                CP_WAIT1();
                __syncthreads();
                if (kt + 2 < 16) issue((kt + 2) % 3, kt + 2);
                CP_COMMIT();

                const __half* As = HSM + (kt % 3) * 15360;
                const __half* Bs = As + 5120;
                #pragma unroll
                for (int ks = 0; ks < 2; ks++) {
                    const int k0 = ks * 16;
                    unsigned af[4][4], bf[8][2];
                    #pragma unroll
                    for (int mt = 0; mt < 4; mt++) {
                        const int rb2 = wm + mt * 16 + g;
                        af[mt][0] = ldh2(&As[rb2 * 40 + k0 + cc2]);
                        af[mt][1] = ldh2(&As[(rb2 + 8) * 40 + k0 + cc2]);
                        af[mt][2] = ldh2(&As[rb2 * 40 + k0 + cc2 + 8]);
                        af[mt][3] = ldh2(&As[(rb2 + 8) * 40 + k0 + cc2 + 8]);
                    }
                    #pragma unroll
                    for (int nt = 0; nt < 8; nt++) {
                        const int nb2 = wn + nt * 8 + g;
                        bf[nt][0] = ldh2(&Bs[nb2 * 40 + k0 + cc2]);
                        bf[nt][1] = ldh2(&Bs[nb2 * 40 + k0 + cc2 + 8]);
                    }
                    #pragma unroll
                    for (int mt = 0; mt < 4; mt++)
                        #pragma unroll
                        for (int nt = 0; nt < 8; nt++) mma16(acc[mt][nt], af[mt], bf[nt]);
                }
            }
            __syncthreads();

            // epilogue: 4 passes of 64 cols through stage (alias SM as float)
            float* stage = (float*)HSM;   // 128*68 floats = 34816B <= 92160B
            const int rr = tid >> 1, half = tid & 1;
            const int gid = rowgid[rr];
            #pragma unroll
            for (int p = 0; p < 4; p++) {
                if ((warp >> 1) == p) {
                    #pragma unroll
                    for (int mt = 0; mt < 4; mt++)
                        #pragma unroll
                        for (int nt = 0; nt < 8; nt++) {
                            const int row = wm + mt * 16 + g, col = nt * 8 + cc * 2;
                            *(float2*)&stage[row * 68 + col]       = make_float2(acc[mt][nt][0], acc[mt][nt][1]);
                            *(float2*)&stage[(row + 8) * 68 + col] = make_float2(acc[mt][nt][2], acc[mt][nt][3]);
                        }
                }
                __syncthreads();

                if (cb < 6) {
                    // bilinear pooling: this 64-col slab = pool group cb*4+p
                    float v = 0.f;
                    if (gid >= 0) {
                        const float* lwp = g_LW + (size_t)gid * GJ + (cb << 8) + p * 64 + half * 32;
                        #pragma unroll
                        for (int i = 0; i < 8; i++) {
                            float4 l4 = *(const float4*)(lwp + i * 4);
                            float4 c4 = *(float4*)&stage[rr * 68 + half * 32 + i * 4];
                            v += c4.x * l4.x + c4.y * l4.y + c4.z * l4.z + c4.w * l4.w;
                        }
                    }
                    v += __shfl_xor_sync(0xffffffffu, v, 1);
                    if (half == 0 && gid >= 0) g_pooled[(size_t)gid * 24 + cb * 4 + p] = v;
                } else {
                    if (gid >= 0) {
                        const int j0 = ((cb - 6) << 8) + p * 64 + half * 32;
                        #pragma unroll
                        for (int i = 0; i < 8; i++) {
                            float4 c4 = *(float4*)&stage[rr * 68 + half * 32 + i * 4];
                            *(float4*)(g_rlin + (size_t)gid * GJ + j0 + i * 4) = c4;
                        }
                    }
                }
                __syncthreads();
            }
        }

        // grid barrier ------------------------------------------------------
        nbar++;
        __syncthreads();
        if (tid == 0) {
            __threadfence();
            unsigned arrived = atomicAdd(&g_gcnt, 1u);
            if (arrived == ncta - 1u) {
                g_gcnt = 0;
                __threadfence();
                atomicAdd(&g_ggen, 1u);
            } else {
                while ((*(volatile unsigned*)&g_ggen) - base < nbar) { }
            }
            __threadfence();
        }
        __syncthreads();

        // ---------------- phase 2: gate assembly + activations --------------
        for (int r2 = blockIdx.x; r2 < R; r2 += ncta) {
            const int gid = g_nodelist[s + r2];
            const int b = gid >> 9, t = gid & 511;
            const int par = nc[(b << 9) + t];
            const bool hasp = (t > 0 && par < t);
            const size_t pbase = hasp ? ((size_t)((b << 9) + par) << 9) : 0;
            const size_t ubase = (size_t)gid * GJ;
            const size_t obase = (size_t)gid << 9;

            float pl[24];
            {
                const float4* pp = (const float4*)(g_pooled + (size_t)gid * 24);
                #pragma unroll
                for (int i = 0; i < 6; i++) {
                    float4 q = pp[i];
                    pl[i * 4] = q.x; pl[i * 4 + 1] = q.y; pl[i * 4 + 2] = q.z; pl[i * 4 + 3] = q.w;
                }
            }

            #pragma unroll
            for (int hh = 0; hh < 2; hh++) {
                const int h = (hh << 8) + tid;
                float gate[3];
                #pragma unroll
                for (int gg = 0; gg < 3; gg++) {
                    float sg = g_Ubuf[ubase + (gg << 9) + h] + g_rlin[ubase + (gg << 9) + h];
                    const float* wop = wo + (((size_t)(gg << 9) + h) << 3);
                    float4 w0 = *(const float4*)(wop);
                    float4 w1 = *(const float4*)(wop + 4);
                    sg += pl[(gg << 3) + 0] * w0.x + pl[(gg << 3) + 1] * w0.y
                        + pl[(gg << 3) + 2] * w0.z + pl[(gg << 3) + 3] * w0.w
                        + pl[(gg << 3) + 4] * w1.x + pl[(gg << 3) + 5] * w1.y
                        + pl[(gg << 3) + 6] * w1.z + pl[(gg << 3) + 7] * w1.w;
                    gate[gg] = sg;
                }
                const float f = 1.f / (1.f + expf(-gate[0]));
                const float o = 1.f / (1.f + expf(-gate[1]));
                const float z = tanhf(gate[2]);
                const float pc = hasp ? g_cbuf[pbase + h] : 0.f;
                const float c = pc * f + (1.f - f) * z;
                const float hv = o * tanhf(c);
                g_cbuf[obase + h] = c;
                out[obase + h] = hv;
                g_hH[obase + h] = __float2half_rn(hv);
            }
        }

        // grid barrier ------------------------------------------------------
        nbar++;
        __syncthreads();
        if (tid == 0) {
            __threadfence();
            unsigned arrived = atomicAdd(&g_gcnt, 1u);
            if (arrived == ncta - 1u) {
                g_gcnt = 0;
                __threadfence();
                atomicAdd(&g_ggen, 1u);
            } else {
                while ((*(volatile unsigned*)&g_ggen) - base < nbar) { }
            }
            __threadfence();
        }
        __syncthreads();
    }
}

// ---------------------------- launch ----------------------------------------
extern "C" void kernel_launch(void* const* d_in, const int* in_sizes, int n_in,
                              void* d_out, int out_size)
{
    (void)in_sizes; (void)n_in; (void)out_size;
    const float* emb  = (const float*)d_in[0];
    const int*   nc   = (const int*)d_in[1];
    // d_in[2] = node_mask (unused by reference)
    const float* wl   = (const float*)d_in[3];
    const float* wr   = (const float*)d_in[4];
    const float* wo   = (const float*)d_in[5];
    const float* ul   = (const float*)d_in[6];
    const float* ur   = (const float*)d_in[7];
    const float* bias = (const float*)d_in[8];
    float* out = (float*)d_out;

    // launch order chosen so ncu (-s 5 -c 1) captures scan_levels (index 5)
    {
        const size_t nq = (size_t)MROWS * 512 / 4 + 4 * (NWELEM / 4);
        const int nb = (int)((nq + 255) / 256);
        conv_all<<<nb, 256>>>(emb, ul, wl, wr, ur);       // 0
    }
    build_depth<<<128, 32>>>(nc);                          // 1
    prefix_levels<<<1, 1>>>();                             // 2
    scatter_levels<<<128, 512>>>();                        // 3

    dim3 gp(GJ / 128, MROWS / 128, 2);                     // (12, 512, 2)
    gemm_pre<<<gp, 256>>>(bias);                           // 4

    scan_levels<<<NCTA, 256>>>(out, nc, wo);               // 5
}